// round 15
// baseline (speedup 1.0000x reference)
#include <cuda_runtime.h>

// y[o*48+p, n, m] = sum_i W0[p,i] * t4[o, (n-1)%56, m, i]
// t4[o, n', m, i] = sum_{j,k} xpad[o, j, n', m+k] * W1[j,k,i]  (pad 3 each side, width)
//
// 112 CTAs (one per (o, out-row n)), 224 threads = 7 warps, ONE block barrier.
// Warp w owns m in [8w, 8w+8). Stage-3 W0 operands prefetched into registers
// right after the barrier. Phase-1 loads fully vectorized / spread across warps.

#define NCH 12
#define WID 56
#define XS 64               // xs row stride; xpad[q] at xs[j*64+q]; zeros [0,3)+[59,62)
#define KS 7
#define NI 9
#define NP 48
#define T4W 80              // per-warp t4 region stride: [i][8] padded
#define THREADS 224

__global__ __launch_bounds__(THREADS, 1)
void fused_sepconv_kernel(const float* __restrict__ x,
                          const float* __restrict__ W0,
                          const float* __restrict__ W1,
                          float* __restrict__ out) {
    __shared__ alignas(16) float xs[NCH * XS];        // 768
    __shared__ alignas(16) float w1s[NCH * KS * NI];  // 756
    __shared__ alignas(16) float w0s[NP * NI];        // 432
    __shared__ alignas(16) float t4s[7 * T4W];        // 560: warp-private [i][8] slices

    const int b = blockIdx.x;             // 0..111
    const int o = b / WID;
    const int n = b % WID;
    const int nin = (n + WID - 1) % WID;  // roll(+1) along height
    const int t = threadIdx.x;
    const int w = t >> 5;                 // warp 0..6
    const int l = t & 31;

    // ---- Phase 1: all global loads issued first (max MLP), then scatter ----
    // t in [0,168):   one x float4  (warps 0-5 + 8 lanes of warp 5)
    // t in [0,108):   one W0 float4 (second independent load on warps 0-3)
    // t in [168,224): W1: 56 threads x up to 4 float4 (189 quads)
    float4 xv = make_float4(0.f, 0.f, 0.f, 0.f);
    float4 w0v = make_float4(0.f, 0.f, 0.f, 0.f);
    float4 w1v0, w1v1, w1v2, w1v3;
    if (t < 168) {
        int j  = t / 14;
        int q4 = t % 14;
        xv = *(const float4*)&x[(((o * NCH + j) * WID + nin) * WID) + 4 * q4];
    }
    if (t < 108) w0v = *(const float4*)&W0[4 * t];
    if (t >= 168) {
        const int e = t - 168;            // 0..55
        w1v0 = *(const float4*)&W1[4 * e];
        w1v1 = *(const float4*)&W1[4 * (e + 56)];
        w1v2 = *(const float4*)&W1[4 * (e + 112)];
        if (e < 21) w1v3 = *(const float4*)&W1[4 * (e + 168)];
    }

    if (t < 168) {
        int j  = t / 14;
        int q4 = t % 14;
        float* dst = &xs[j * XS + 3 + 4 * q4];   // x col c -> xs idx c+3 (== xpad idx)
        dst[0] = xv.x; dst[1] = xv.y; dst[2] = xv.z; dst[3] = xv.w;
        if (q4 == 0) {
            xs[j * XS + 0] = 0.f; xs[j * XS + 1] = 0.f; xs[j * XS + 2] = 0.f;
        } else if (q4 == 13) {
            xs[j * XS + 59] = 0.f; xs[j * XS + 60] = 0.f; xs[j * XS + 61] = 0.f;
        }
    }
    if (t < 108) *(float4*)&w0s[4 * t] = w0v;
    if (t >= 168) {
        const int e = t - 168;
        *(float4*)&w1s[4 * e]          = w1v0;
        *(float4*)&w1s[4 * (e + 56)]   = w1v1;
        *(float4*)&w1s[4 * (e + 112)]  = w1v2;
        if (e < 21) *(float4*)&w1s[4 * (e + 168)] = w1v3;
    }

    __syncthreads();   // the ONLY block barrier

    // ---- Prefetch stage-3 W0 rows into registers (independent of t4) ----
    float w0r[3][NI];
    #pragma unroll
    for (int r = 0; r < 3; ++r) {
        const int p = (r * 32 + l) % NP;
        #pragma unroll
        for (int i = 0; i < NI; ++i)
            w0r[r][i] = w0s[p * NI + i];   // stride-9 reads, conflict-free
    }

    // ---- Stage 2 (warp-local): lanes 0..17 = (quad q, i); 4-m quad per lane ----
    if (l < 18) {
        const int q  = l / NI;            // 0,1
        const int i  = l % NI;            // lanes i-fast: w1 reads consecutive
        const int m0 = 8 * w + 4 * q;     // global m base of this quad

        float a0 = 0.f, a1 = 0.f, a2 = 0.f, a3 = 0.f;  // outputs m0..m0+3

        #pragma unroll
        for (int j = 0; j < NCH; ++j) {
            // window xpad[m0 .. m0+9] = 5 aligned float2
            const float2* xg = (const float2*)&xs[j * XS + m0];
            float2 g0 = xg[0], g1 = xg[1], g2 = xg[2], g3 = xg[3], g4 = xg[4];
            const float xw[10] = {g0.x, g0.y, g1.x, g1.y, g2.x,
                                  g2.y, g3.x, g3.y, g4.x, g4.y};
            const float* wj = &w1s[(j * KS) * NI + i];

            #pragma unroll
            for (int k = 0; k < KS; ++k) {
                const float wv = wj[k * NI];
                a0 = fmaf(xw[k],     wv, a0);
                a1 = fmaf(xw[k + 1], wv, a1);
                a2 = fmaf(xw[k + 2], wv, a2);
                a3 = fmaf(xw[k + 3], wv, a3);
            }
        }
        *(float4*)&t4s[w * T4W + i * 8 + 4 * q] = make_float4(a0, a1, a2, a3);
    }

    __syncwarp();      // warp-local producer->consumer hand-off

    // ---- Stage 3 (warp-local): 96 float4 outputs per warp, 3 per lane ----
    #pragma unroll
    for (int r = 0; r < 3; ++r) {
        const int idx = r * 32 + l;       // 0..95
        const int p   = idx % NP;
        const int mq  = idx / NP;         // 0,1
        const int m0  = 8 * w + 4 * mq;

        float4 res = make_float4(0.f, 0.f, 0.f, 0.f);
        float* rp = (float*)&res;
        #pragma unroll
        for (int i = 0; i < NI; ++i) {
            float4 tq = *(const float4*)&t4s[w * T4W + i * 8 + 4 * mq];  // broadcast
            const float wv = w0r[r][i];   // register, no LDS
            rp[0] = fmaf(tq.x, wv, rp[0]);
            rp[1] = fmaf(tq.y, wv, rp[1]);
            rp[2] = fmaf(tq.z, wv, rp[2]);
            rp[3] = fmaf(tq.w, wv, rp[3]);
        }
        *(float4*)&out[(((o * NP + p) * WID + n) * WID) + m0] = res;
    }
}

extern "C" void kernel_launch(void* const* d_in, const int* in_sizes, int n_in,
                              void* d_out, int out_size) {
    // Bind inputs by size: x=75264, W0=432, W1=756
    const float* x  = (const float*)d_in[0];
    const float* W0 = (const float*)d_in[1];
    const float* W1 = (const float*)d_in[2];
    for (int i = 0; i < n_in; ++i) {
        if (in_sizes[i] == 75264) x  = (const float*)d_in[i];
        else if (in_sizes[i] == 432) W0 = (const float*)d_in[i];
        else if (in_sizes[i] == 756) W1 = (const float*)d_in[i];
    }
    float* out = (float*)d_out;

    fused_sepconv_kernel<<<2 * WID, THREADS>>>(x, W0, W1, out);
}